// round 13
// baseline (speedup 1.0000x reference)
#include <cuda_runtime.h>
#include <cuda_bf16.h>
#include <math.h>

#define BTOT 32768
#define K 64
#define D 64
#define NF 2176            // padded feature count (136 k-steps of 16)
#define NG 1088            // feature groups of 2
#define NKS 136
#define NBLK_MAIN 256      // 128 samples per CTA, 256 threads (8 warps x 16 rows)

typedef unsigned long long ull;

// ---------------- device scratch (no allocs) ----------------
// B operand in mma.sync fragment-linear layout:
// entry e = (kstep*8 + ntile)*32 + lane, 8 bytes = {b0(lo32), b1(hi32)}
__device__ ull      d_Wf[NKS * 8 * 32];
__device__ float    d_g[K];
__device__ float    d_partial[NBLK_MAIN];
__device__ unsigned d_count = 0;

// ---------------- helpers ----------------
__device__ __forceinline__ ull fma2(ull a, ull b, ull c) {
    ull d; asm("fma.rn.f32x2 %0, %1, %2, %3;" : "=l"(d) : "l"(a), "l"(b), "l"(c)); return d;
}
__device__ __forceinline__ float hadd2(ull a) {
    float lo, hi; asm("mov.b64 {%0, %1}, %2;" : "=f"(lo), "=f"(hi) : "l"(a)); return lo + hi;
}
__device__ __forceinline__ ull pack2(float lo, float hi) {
    ull d; asm("mov.b64 %0, {%1, %2};" : "=l"(d) : "f"(lo), "f"(hi)); return d;
}
__device__ __forceinline__ void lds2(ull& a, ull& b, unsigned addr) {
    asm("ld.shared.v2.b64 {%0, %1}, [%2];" : "=l"(a), "=l"(b) : "r"(addr));
}
// packs: lower 16 bits <- lo, upper <- hi (first PTX src goes to upper half)
__device__ __forceinline__ unsigned cvt_bf16x2(float lo, float hi) {
    unsigned r;
    asm("cvt.rn.satfinite.bf16x2.f32 %0, %1, %2;" : "=r"(r) : "f"(hi), "f"(lo));
    return r;
}
__device__ __forceinline__ void mma_bf16(float& c0, float& c1, float& c2, float& c3,
                                         unsigned a0, unsigned a1, unsigned a2, unsigned a3,
                                         unsigned b0, unsigned b1) {
    asm volatile("mma.sync.aligned.m16n8k16.row.col.f32.bf16.bf16.f32 "
                 "{%0,%1,%2,%3}, {%4,%5,%6,%7}, {%8,%9}, {%0,%1,%2,%3};"
                 : "+f"(c0), "+f"(c1), "+f"(c2), "+f"(c3)
                 : "r"(a0), "r"(a1), "r"(a2), "r"(a3), "r"(b0), "r"(b1));
}

// ---------------------------------------------------------------------------
// Group table (closed form). Group g -> code (i<<8)|j0 meaning feature columns
// 2g = x_i * x_j0, 2g+1 = x_i * x_(j0+1).
//   g < 32:   (64, 2g)  -> linear features (x[64]=1)
//   g >= 32:  lower-tri rows, row i has floor(i/2)+1 groups; j0+1 > i is a
//             pad column (weight 0 in W).
// C(i) = prefix group count: i=2m -> m(m+1); i=2m+1 -> (m+1)^2.
// ---------------------------------------------------------------------------
__device__ __forceinline__ int Cgrp(int t) {
    int m = t >> 1;
    return (t & 1) ? (m + 1) * (m + 1) : m * (m + 1);
}
__device__ __forceinline__ int group_code(int g) {
    if (g < 32) return (64 << 8) | (2 * g);
    int G = g - 32;
    int i = (int)sqrtf(4.0f * (float)G + 1.0f) - 1;
    if (i < 0) i = 0;
    if (i > 63) i = 63;
    while (i < 63 && Cgrp(i + 1) <= G) ++i;
    while (Cgrp(i) > G) --i;
    int j0 = (G - Cgrp(i)) * 2;
    return (i << 8) | j0;
}

// ---------------------------------------------------------------------------
// prep: one 128-thread block per component k.
//   L -> Linv (forward substitution), A = Linv^T Linv, b = A mu, g.
//   Tail reductions (half-log-det, mu.b, weight softmax) via warp shuffles.
//   Weights written to d_Wf in mma.sync B-fragment layout (bf16).
// ---------------------------------------------------------------------------
__global__ __launch_bounds__(128) void prep_kernel(const float* __restrict__ scale_raw,
                                                   const float* __restrict__ means_raw,
                                                   const float* __restrict__ weights_raw) {
    const int k = blockIdx.x;
    const int tid = threadIdx.x;

    __shared__ float Ls[D][D];     // L; later holds A
    __shared__ float VT[D][68];    // VT[j][i] = Linv[i][j] (16B-aligned stride)
    __shared__ float rdiag[D], ms[D], pdiag[D], bsm[D], wsh[D];
    __shared__ float wstage[K];
    __shared__ float bp2[128];

    const float sc2 = 1.0f / 512.0f;
    const float sc1 = 1.0f / 64.0f;

    for (int idx = tid; idx < D * D; idx += 128) {
        int i = idx >> 6, jj = idx & 63;
        float p = scale_raw[(size_t)k * D * D + idx] * sc2;
        float v;
        if (jj < i) v = p;
        else if (jj == i) { float e = expf(p); v = e; pdiag[i] = p; rdiag[i] = 1.0f / e; }
        else v = 0.0f;
        Ls[i][jj] = v;
    }
    if (tid < D) ms[tid] = means_raw[k * D + tid] * sc1;
    if (tid < K) wstage[tid] = weights_raw[tid] * 0.125f;
    __syncthreads();

    // forward substitution: thread j (<64) computes column j into VT[j][*]
    if (tid < D) {
        const int j = tid;
        float prev = 0.0f;
        #pragma unroll 1
        for (int i = 0; i < D; ++i) {
            const float* Lrow = &Ls[i][0];
            const int e = i - 1;
            const int mend = (e > 0) ? (e & ~3) : 0;
            float a0 = 0.f, a1 = 0.f, a2 = 0.f, a3 = 0.f;
            #pragma unroll 1
            for (int m = 0; m < mend; m += 4) {
                float4 vm = *(const float4*)&VT[j][m];
                a0 = fmaf(Lrow[m + 0], vm.x, a0);
                a1 = fmaf(Lrow[m + 1], vm.y, a1);
                a2 = fmaf(Lrow[m + 2], vm.z, a2);
                a3 = fmaf(Lrow[m + 3], vm.w, a3);
            }
            for (int m = mend; m < e; ++m) a0 = fmaf(Lrow[m], VT[j][m], a0);
            float s = (a0 + a1) + (a2 + a3);
            if (i > 0) s = fmaf(Lrow[e], prev, s);
            float de = (j == i) ? 1.0f : 0.0f;
            float vi = (de - s) * rdiag[i];
            VT[j][i] = vi;
            prev = vi;
        }
    }
    __syncthreads();

    // A rows: thread (jj, h): A[jj][q] for q in [32h, 32h+32)
    const int jj = tid & 63, h = tid >> 6;
    ull vp[32];
    {
        const float4* myrow = (const float4*)&VT[jj][0];
        #pragma unroll
        for (int c = 0; c < 16; ++c) {
            float4 v4 = myrow[c];
            vp[2 * c + 0] = pack2(v4.x, v4.y);
            vp[2 * c + 1] = pack2(v4.z, v4.w);
        }
    }
    float bpart = 0.0f;
    const unsigned vtb = (unsigned)__cvta_generic_to_shared(&VT[0][0]);
    #pragma unroll 2
    for (int qq = 0; qq < 32; ++qq) {
        const int q = h * 32 + qq;
        const unsigned qa = vtb + (unsigned)q * 272u;
        ull acc = 0ULL;
        #pragma unroll
        for (int c = 0; c < 16; ++c) {
            ull w0, w1;
            lds2(w0, w1, qa + 16u * c);
            acc = fma2(w0, vp[2 * c + 0], acc);
            acc = fma2(w1, vp[2 * c + 1], acc);
        }
        float a = hadd2(acc);
        Ls[jj][q] = a;                       // overwrite L with A
        bpart = fmaf(a, ms[q], bpart);
    }
    bp2[tid] = bpart;
    __syncthreads();
    if (tid < D) {
        float bj = bp2[tid] + bp2[tid + 64];
        bsm[tid] = bj;
        wsh[tid] = ms[tid] * bj;             // mu_j * b_j
    }
    __syncthreads();

    // tail reductions in warp 0 (shfl), not one serial thread
    if (tid < 32) {
        float h2 = pdiag[tid] + pdiag[tid + 32];          // -> half-log-det
        float c2 = wsh[tid] + wsh[tid + 32];              // -> mu.b
        float w1 = wstage[tid], w2 = wstage[tid + 32];
        float wm = fmaxf(w1, w2);
        #pragma unroll
        for (int o = 16; o > 0; o >>= 1) wm = fmaxf(wm, __shfl_xor_sync(0xFFFFFFFFu, wm, o));
        float es = __expf(w1 - wm) + __expf(w2 - wm);
        #pragma unroll
        for (int o = 16; o > 0; o >>= 1) {
            es += __shfl_xor_sync(0xFFFFFFFFu, es, o);
            h2 += __shfl_xor_sync(0xFFFFFFFFu, h2, o);
            c2 += __shfl_xor_sync(0xFFFFFFFFu, c2, o);
        }
        if (tid == 0) {
            float logwk = wstage[k] - (wm + logf(es));
            const float HALF_D_LOG2PI = 0.5f * 64.0f * 1.8378770664093453f;
            d_g[k] = logwk - h2 - HALF_D_LOG2PI - 0.5f * c2;
        }
    }

    // W scatter into B-fragment layout (paired-group feature ordering)
    for (int f = tid; f < NF; f += 128) {
        int g = f >> 1, p = f & 1;
        int code = group_code(g);
        int i = code >> 8, j = (code & 255) + p;
        float w;
        if (i == 64)      w = bsm[j];                         // linear: b_j
        else if (j > i)   w = 0.0f;                           // pad
        else if (j == i)  w = -0.5f * (Ls[i][i] - 1.0f);      // -0.5*E_diag
        else              w = -Ls[i][j];                      // -E_offdiag (j<i)
        int ks = f >> 4, within = f & 15;
        int hh = within >> 3, bb2 = within & 1, qq = (within & 7) >> 1;
        int lane = ((k & 7) << 2) | qq;
        int e = (ks * 8 + (k >> 3)) * 32 + lane;
        ((__nv_bfloat16*)d_Wf)[e * 4 + hh * 2 + bb2] = __float2bfloat16(w);
    }
}

// ---------------------------------------------------------------------------
// main: 256 CTAs x 256 threads (8 warps). Warp w owns rows w*16..w*16+15,
// all 64 comps: scores[128,64] = F[128,2176] @ Wf^T via mma.sync bf16.
// One m-tile per warp -> acc 32 regs -> 2 CTAs/SM co-resident (one wave).
// ---------------------------------------------------------------------------
#define DO_STEP(KS, BARR)                                                     \
    do {                                                                      \
        const int gA = (KS) * 8 + q, gB = gA + 4;                             \
        const int t0 = sgrp[gA], t1 = sgrp[gB];                               \
        const int iA = t0 >> 8, jA = t0 & 255;                                \
        const int iB = t1 >> 8, jB = t1 & 255;                                \
        unsigned a0[4];                                                       \
        {                                                                     \
            float  sA0 = rp0[iA]; float2 vA0 = *(const float2*)(rp0 + jA);    \
            float  sA1 = rp1[iA]; float2 vA1 = *(const float2*)(rp1 + jA);    \
            float  sB0 = rp0[iB]; float2 vB0 = *(const float2*)(rp0 + jB);    \
            float  sB1 = rp1[iB]; float2 vB1 = *(const float2*)(rp1 + jB);    \
            a0[0] = cvt_bf16x2(sA0 * vA0.x, sA0 * vA0.y);                     \
            a0[1] = cvt_bf16x2(sA1 * vA1.x, sA1 * vA1.y);                     \
            a0[2] = cvt_bf16x2(sB0 * vB0.x, sB0 * vB0.y);                     \
            a0[3] = cvt_bf16x2(sB1 * vB1.x, sB1 * vB1.y);                     \
        }                                                                     \
        _Pragma("unroll")                                                     \
        for (int nt = 0; nt < 8; ++nt) {                                      \
            const unsigned b0 = (unsigned)(BARR[nt] & 0xFFFFFFFFu);           \
            const unsigned b1 = (unsigned)(BARR[nt] >> 32);                   \
            mma_bf16(acc[nt][0], acc[nt][1], acc[nt][2], acc[nt][3],          \
                     a0[0], a0[1], a0[2], a0[3], b0, b1);                     \
        }                                                                     \
    } while (0)

__global__ __launch_bounds__(256, 2) void gmm_main(const float* __restrict__ x,
                                                   float* __restrict__ out) {
    __shared__ float xs[128][68];      // row: 64 x values, [64]=1
    __shared__ float xxs[128];
    __shared__ float gs[K];
    __shared__ int   sgrp[NG];
    __shared__ float red[256];
    __shared__ unsigned sflag;

    const int tid = threadIdx.x;
    const int wid = tid >> 5, lane = tid & 31;
    const int q = lane & 3, ro = lane >> 2;

    // group table (closed form)
    for (int g = tid; g < NG; g += 256) sgrp[g] = group_code(g);

    // threads 0-127 load sample rows, accumulate ||x||^2
    if (tid < 128) {
        const float4* xg = (const float4*)(x + ((size_t)blockIdx.x * 128 + tid) * D);
        float xx = 0.0f;
        float4* xrow = (float4*)&xs[tid][0];
        #pragma unroll
        for (int i = 0; i < 16; ++i) {
            float4 v = xg[i];
            xrow[i] = v;
            xx = fmaf(v.x, v.x, xx); xx = fmaf(v.y, v.y, xx);
            xx = fmaf(v.z, v.z, xx); xx = fmaf(v.w, v.w, xx);
        }
        xs[tid][64] = 1.0f; xs[tid][65] = 0.0f;
        xxs[tid] = xx;
    }
    if (tid < K) gs[tid] = d_g[tid];
    __syncthreads();

    const int wbase = wid * 16;
    const float* rp0 = &xs[wbase + ro][0];        // rows for c0/c1
    const float* rp1 = &xs[wbase + ro + 8][0];    // rows for c2/c3

    float acc[8][4];
    #pragma unroll
    for (int nt = 0; nt < 8; ++nt)
        #pragma unroll
        for (int c = 0; c < 4; ++c) acc[nt][c] = 0.0f;

    const ull* wf = d_Wf + lane;

    // B double buffer, unroll-2 rotation
    ull bA[8], bB[8];
    #pragma unroll
    for (int nt = 0; nt < 8; ++nt) bA[nt] = wf[nt * 32];

    #pragma unroll 1
    for (int ks = 0; ks < NKS; ks += 2) {
        #pragma unroll
        for (int nt = 0; nt < 8; ++nt) bB[nt] = wf[(ks + 1) * 256 + nt * 32];
        DO_STEP(ks, bA);
        const int k2 = (ks + 2 < NKS) ? ks + 2 : NKS - 1;
        #pragma unroll
        for (int nt = 0; nt < 8; ++nt) bA[nt] = wf[k2 * 256 + nt * 32];
        DO_STEP(ks + 1, bB);
    }

    // epilogue: per thread 2 rows x 16 comps; quad-shuffle LSE per row
    float lpsum = 0.0f;
    #pragma unroll
    for (int hf = 0; hf < 2; ++hf) {
        const int row = wbase + ro + 8 * hf;
        const float cxx = -0.5f * xxs[row];
        float v[16];
        float m = -1e30f;
        #pragma unroll
        for (int nt = 0; nt < 8; ++nt) {
            #pragma unroll
            for (int cc = 0; cc < 2; ++cc) {
                float val = acc[nt][hf * 2 + cc] + gs[nt * 8 + q * 2 + cc] + cxx;
                v[nt * 2 + cc] = val;
                m = fmaxf(m, val);
            }
        }
        m = fmaxf(m, __shfl_xor_sync(0xFFFFFFFFu, m, 1));
        m = fmaxf(m, __shfl_xor_sync(0xFFFFFFFFu, m, 2));
        float s = 0.0f;
        #pragma unroll
        for (int u = 0; u < 16; ++u) s += __expf(v[u] - m);
        s += __shfl_xor_sync(0xFFFFFFFFu, s, 1);
        s += __shfl_xor_sync(0xFFFFFFFFu, s, 2);
        lpsum += m + logf(s);
    }
    red[tid] = (q == 0) ? lpsum : 0.0f;
    __syncthreads();
    #pragma unroll
    for (int s = 128; s > 0; s >>= 1) {
        if (tid < s) red[tid] += red[tid + s];
        __syncthreads();
    }
    if (tid == 0) {
        d_partial[blockIdx.x] = red[0];
        __threadfence();
        unsigned ticket = atomicAdd(&d_count, 1u);
        sflag = (ticket == (unsigned)(NBLK_MAIN - 1)) ? 1u : 0u;
    }
    __syncthreads();

    // last CTA: final deterministic reduction + counter reset
    if (sflag) {
        __threadfence();
        red[tid] = d_partial[tid];
        __syncthreads();
        #pragma unroll
        for (int s = 128; s > 0; s >>= 1) {
            if (tid < s) red[tid] += red[tid + s];
            __syncthreads();
        }
        if (tid == 0) {
            out[0] = -red[0] / (float)BTOT;
            d_count = 0;                      // reset for next graph replay
        }
    }
}

extern "C" void kernel_launch(void* const* d_in, const int* in_sizes, int n_in,
                              void* d_out, int out_size) {
    const float* x      = (const float*)d_in[0];
    const float* means  = (const float*)d_in[1];
    const float* scale  = (const float*)d_in[2];
    const float* wraw   = (const float*)d_in[3];

    prep_kernel<<<K, 128>>>(scale, means, wraw);
    gmm_main<<<NBLK_MAIN, 256>>>(x, (float*)d_out);
}